// round 8
// baseline (speedup 1.0000x reference)
#include <cuda_runtime.h>
#include <math.h>

#define NS 1024
#define HD 256
#define XD 128
#define S2 34     // phase-2 smem row stride in float2 units (conflict-free LDS.128 phases)
#define NCTA 256

// device scratch (no allocations allowed)
__device__ __align__(16) float g_xp[NS * HD];   // x @ Wx
__device__ __align__(16) float g_yp[NS * HD];   // y @ Wy + b1
__device__ double g_pe[NCTA];
__device__ double g_pd[NCTA];
__device__ unsigned int c_bar;    // phase barrier arrivals (reset by final CTA)
__device__ unsigned int c_done;   // completion counter    (reset by final CTA)

typedef unsigned long long u64;

__device__ __forceinline__ u64 pk2(float a, float b) {
    u64 r; asm("mov.b64 %0, {%1, %2};" : "=l"(r) : "f"(a), "f"(b)); return r;
}
__device__ __forceinline__ void up2(u64 v, float& a, float& b) {
    asm("mov.b64 {%0, %1}, %2;" : "=f"(a), "=f"(b) : "l"(v));
}
__device__ __forceinline__ u64 fma2(u64 a, u64 b, u64 c) {
    u64 r; asm("fma.rn.f32x2 %0, %1, %2, %3;" : "=l"(r) : "l"(a), "l"(b), "l"(c)); return r;
}

// acc += relu(xv + yv) * w, packed f32x2 (4 SASS instrs: ADD2, 2x FMAX, FFMA2)
__device__ __forceinline__ void step(u64 xv, u64 yv, u64 w, u64& acc) {
    asm("{\n\t"
        ".reg .f32 lo, hi;\n\t"
        ".reg .b64 s;\n\t"
        "add.rn.f32x2 s, %1, %2;\n\t"
        "mov.b64 {lo, hi}, s;\n\t"
        "max.f32 lo, lo, 0f00000000;\n\t"
        "max.f32 hi, hi, 0f00000000;\n\t"
        "mov.b64 s, {lo, hi};\n\t"
        "fma.rn.f32x2 %0, s, %3, %0;\n\t"
        "}" : "+l"(acc) : "l"(xv), "l"(yv), "l"(w));
}

__global__ void __launch_bounds__(256, 2) k_fused(
    const float* __restrict__ x, const float* __restrict__ y,
    const float* __restrict__ W1, const float* __restrict__ b1,
    const float* __restrict__ W2, const float* __restrict__ b2,
    float* __restrict__ out)
{
    __shared__ __align__(16) float2 xsh[64 * S2];  // phase 2 j rows; phase 1 aliases front
    __shared__ __align__(16) float2 ysh[64 * S2];  // phase 2 i rows
    __shared__ __align__(16) float2 wsh[128];
    __shared__ float rr[16];
    __shared__ double dr[16];
    __shared__ int donesh;

    int t = threadIdx.x;
    int cta = blockIdx.x;

    // ---------------- Phase 1: projections (8 rows per CTA) ----------------
    {
        float* xs = (float*)xsh;                 // needs 128*10 floats = 5120 B
        int isY = cta >> 7;
        int row0 = (cta & 127) << 3;
        const float* src = isY ? y : x;
        const float* W = W1 + isY * (XD * HD);

        #pragma unroll
        for (int p = 0; p < 4; p++) {
            int idx = t + p * 256;               // 0..1023
            int r = idx >> 7, k = idx & 127;
            xs[k * 10 + r] = src[(row0 + r) * XD + k];
        }
        __syncthreads();

        u64 acc1[4];
        #pragma unroll
        for (int m = 0; m < 4; m++) acc1[m] = 0ull;

        #pragma unroll 8
        for (int k = 0; k < 128; k++) {
            float w = W[k * HD + t];
            u64 wd = pk2(w, w);
            #pragma unroll
            for (int m = 0; m < 4; m++)
                acc1[m] = fma2(*(const u64*)&xs[k * 10 + 2 * m], wd, acc1[m]);
        }

        float bias = isY ? b1[t] : 0.0f;
        float* dst = isY ? g_yp : g_xp;
        #pragma unroll
        for (int m = 0; m < 4; m++) {
            float v0, v1; up2(acc1[m], v0, v1);
            dst[(row0 + 2 * m)     * HD + t] = v0 + bias;
            dst[(row0 + 2 * m + 1) * HD + t] = v1 + bias;
        }
    }

    // ---------------- device-wide barrier (arrive: atomic; wait: LOAD poll) ----------------
    __threadfence();
    __syncthreads();
    if (t == 0) {
        atomicAdd(&c_bar, 1u);                       // one atomic per CTA
        volatile unsigned int* vb = &c_bar;          // poll with plain loads (L2 broadcast)
        while (*vb < (unsigned)NCTA) __nanosleep(64);
    }
    __syncthreads();
    __threadfence();

    // ---------------- Phase 2: one 64x64 pair tile per CTA (R7-proven) ----------------
    if (t < 128) wsh[t] = ((const float2*)W2)[t];

    int tx = t & 15, ty = t >> 4;
    int jT = (cta & 15) << 6, iT = (cta >> 4) << 6;

    const float4* gx = (const float4*)g_xp;
    const float4* gy = (const float4*)g_yp;
    float4* xs4 = (float4*)xsh;                  // 17 f4 per row
    float4* ys4 = (float4*)ysh;

    u64 acc[16];
    #pragma unroll
    for (int p = 0; p < 16; p++) acc[p] = 0ull;

    #pragma unroll 1
    for (int ch = 0; ch < 4; ch++) {
        __syncthreads();
        #pragma unroll
        for (int p = 0; p < 4; p++) {
            int idx = t + p * 256;
            int row = idx >> 4, c4 = idx & 15;
            xs4[row * 17 + c4] = gx[(jT + row) * 64 + ch * 16 + c4];
            ys4[row * 17 + c4] = gy[(iT + row) * 64 + ch * 16 + c4];
        }
        __syncthreads();

        #pragma unroll 8
        for (int j2 = 0; j2 < 16; j2++) {        // 4 k per iter
            ulonglong2 wv = *(const ulonglong2*)&wsh[ch * 32 + 2 * j2];
            ulonglong2 xq[4], yq[4];
            #pragma unroll
            for (int a = 0; a < 4; a++)
                xq[a] = *(const ulonglong2*)&xsh[(tx + 16 * a) * S2 + 2 * j2];
            #pragma unroll
            for (int b4 = 0; b4 < 4; b4++)
                yq[b4] = *(const ulonglong2*)&ysh[(ty + 16 * b4) * S2 + 2 * j2];
            #pragma unroll
            for (int b4 = 0; b4 < 4; b4++) {
                #pragma unroll
                for (int a = 0; a < 4; a++) {
                    step(xq[a].x, yq[b4].x, wv.x, acc[b4 * 4 + a]);
                    step(xq[a].y, yq[b4].y, wv.y, acc[b4 * 4 + a]);
                }
            }
        }
    }

    // tile epilogue: per-pair dot -> exp-sum + diagonal capture
    float le = 0.0f, ld = 0.0f;
    #pragma unroll
    for (int b4 = 0; b4 < 4; b4++) {
        #pragma unroll
        for (int a = 0; a < 4; a++) {
            float lo, hi; up2(acc[b4 * 4 + a], lo, hi);
            float s = lo + hi;
            le += __expf(s);
            if (iT + ty + 16 * b4 == jT + tx + 16 * a) ld += s;
        }
    }

    #pragma unroll
    for (int o = 16; o > 0; o >>= 1) {
        le += __shfl_xor_sync(0xffffffffu, le, o);
        ld += __shfl_xor_sync(0xffffffffu, ld, o);
    }
    int wid = t >> 5, lane = t & 31;
    if (lane == 0) { rr[wid] = le; rr[8 + wid] = ld; }
    __syncthreads();
    if (t == 0) {
        float se = 0.0f, sd = 0.0f;
        #pragma unroll
        for (int w8 = 0; w8 < 8; w8++) { se += rr[w8]; sd += rr[8 + w8]; }
        g_pe[cta] = (double)se;                  // plain stores, no contention
        g_pd[cta] = (double)sd;
    }

    // ---------------- completion + final scalar ----------------
    __threadfence();
    __syncthreads();
    if (t == 0) {
        unsigned r = atomicAdd(&c_done, 1u);
        donesh = (r == (unsigned)(NCTA - 1)) ? 1 : 0;
    }
    __syncthreads();

    if (donesh) {
        __threadfence();
        double se = g_pe[t];                     // 256 threads, one partial each
        double sd = g_pd[t];
        #pragma unroll
        for (int o = 16; o > 0; o >>= 1) {
            se += __shfl_xor_sync(0xffffffffu, se, o);
            sd += __shfl_xor_sync(0xffffffffu, sd, o);
        }
        if (lane == 0) { dr[wid] = se; dr[8 + wid] = sd; }
        __syncthreads();
        if (t == 0) {
            double tse = 0.0, tsd = 0.0;
            #pragma unroll
            for (int w8 = 0; w8 < 8; w8++) { tse += dr[w8]; tsd += dr[8 + w8]; }
            double bb = (double)b2[0];
            double lb = tsd / (double)NS + bb
                      - exp(bb - 1.0) * tse / ((double)NS * (double)NS);
            out[0] = (float)lb;
            c_bar = 0u; c_done = 0u;             // reset for next graph replay
        }
    }
}

extern "C" void kernel_launch(void* const* d_in, const int* in_sizes, int n_in,
                              void* d_out, int out_size)
{
    (void)in_sizes; (void)n_in; (void)out_size;
    const float* x  = (const float*)d_in[0];
    const float* y  = (const float*)d_in[1];
    const float* W1 = (const float*)d_in[2];
    const float* b1 = (const float*)d_in[3];
    const float* W2 = (const float*)d_in[4];
    const float* b2 = (const float*)d_in[5];

    k_fused<<<NCTA, 256>>>(x, y, W1, b1, W2, b2, (float*)d_out);
}

// round 9
// speedup vs baseline: 1.1266x; 1.1266x over previous
#include <cuda_runtime.h>
#include <math.h>

#define NS 1024
#define HD 256
#define XD 128
#define S2 34   // k_pair smem row stride in float2 units (conflict-free LDS phases)

// scratch (device globals: no allocation allowed)
__device__ __align__(16) float g_xp[NS * HD];   // x @ Wx
__device__ __align__(16) float g_yp[NS * HD];   // y @ Wy + b1
__device__ double g_es;          // grand exp sum
__device__ double g_ds;          // diagonal sum
__device__ unsigned int g_cnt;   // k_pair completion counter

typedef unsigned long long u64;

__device__ __forceinline__ u64 pk2(float a, float b) {
    u64 r; asm("mov.b64 %0, {%1, %2};" : "=l"(r) : "f"(a), "f"(b)); return r;
}
__device__ __forceinline__ void up2(u64 v, float& a, float& b) {
    asm("mov.b64 {%0, %1}, %2;" : "=f"(a), "=f"(b) : "l"(v));
}
__device__ __forceinline__ u64 fma2(u64 a, u64 b, u64 c) {
    u64 r; asm("fma.rn.f32x2 %0, %1, %2, %3;" : "=l"(r) : "l"(a), "l"(b), "l"(c)); return r;
}

// acc += relu(xv + yv) * w, packed f32x2 (4 SASS instrs: ADD2, 2x FMAX, FFMA2)
__device__ __forceinline__ void step(u64 xv, u64 yv, u64 w, u64& acc) {
    asm("{\n\t"
        ".reg .f32 lo, hi;\n\t"
        ".reg .b64 s;\n\t"
        "add.rn.f32x2 s, %1, %2;\n\t"
        "mov.b64 {lo, hi}, s;\n\t"
        "max.f32 lo, lo, 0f00000000;\n\t"
        "max.f32 hi, hi, 0f00000000;\n\t"
        "mov.b64 s, {lo, hi};\n\t"
        "fma.rn.f32x2 %0, s, %3, %0;\n\t"
        "}" : "+l"(acc) : "l"(xv), "l"(yv), "l"(w));
}

// xp = x @ W1[:128]; yp = y @ W1[128:] + b1.
// 128 blocks (single wave) x 256 threads; 16 rows per block. (R7-proven)
__global__ void __launch_bounds__(256) k_gemm(
    const float* __restrict__ x, const float* __restrict__ y,
    const float* __restrict__ W1, const float* __restrict__ b1)
{
    if (blockIdx.x == 0 && threadIdx.x == 0) { g_es = 0.0; g_ds = 0.0; g_cnt = 0u; }

    __shared__ __align__(16) float xs[128 * 18];
    int b = blockIdx.x;
    int isY = b >> 6;
    int row0 = (b & 63) << 4;
    const float* src = isY ? y : x;
    const float* W = W1 + isY * (XD * HD);
    int t = threadIdx.x;

    #pragma unroll
    for (int p = 0; p < 8; p++) {
        int idx = t + p * 256;
        int r = idx >> 7, k = idx & 127;
        xs[k * 18 + r] = src[(row0 + r) * XD + k];
    }
    __syncthreads();

    u64 acc[8];
    #pragma unroll
    for (int m = 0; m < 8; m++) acc[m] = 0ull;

    #pragma unroll 8
    for (int k = 0; k < 128; k++) {
        float w = W[k * HD + t];
        u64 wd = pk2(w, w);
        #pragma unroll
        for (int m = 0; m < 8; m++)
            acc[m] = fma2(*(const u64*)&xs[k * 18 + 2 * m], wd, acc[m]);
    }

    float bias = isY ? b1[t] : 0.0f;
    float* dst = isY ? g_yp : g_xp;
    #pragma unroll
    for (int m = 0; m < 8; m++) {
        float v0, v1; up2(acc[m], v0, v1);
        dst[(row0 + 2 * m)     * HD + t] = v0 + bias;
        dst[(row0 + 2 * m + 1) * HD + t] = v1 + bias;
    }
}

// Pairwise kernel: 64x64 tile per CTA, *128* threads, 4 CTAs/SM.
// Thread = 8i x 4j x (2k packed). Same smem layout as R7; finer CTA granularity
// so syncs stall 1/4 of the SM and each SMSP draws from 4 independent CTAs.
__global__ void __launch_bounds__(128, 4) k_pair(
    const float* __restrict__ W2, const float* __restrict__ b2,
    float* __restrict__ out)
{
    __shared__ __align__(16) float2 xsh[64 * S2];   // j rows
    __shared__ __align__(16) float2 ysh[64 * S2];   // i rows
    __shared__ __align__(16) float2 wsh[128];
    __shared__ float rr[8];

    int t = threadIdx.x;
    int tx = t & 15, ty = t >> 4;                   // tx: j base, ty: i base (0..7)
    int jT = blockIdx.x << 6, iT = blockIdx.y << 6;

    wsh[t] = ((const float2*)W2)[t];                // 128 threads load all 128 f2

    const float4* gx = (const float4*)g_xp;         // 64 f4 per 256-float row
    const float4* gy = (const float4*)g_yp;
    float4* xs4 = (float4*)xsh;                     // 17 f4 per row (= S2 f2)
    float4* ys4 = (float4*)ysh;

    u64 acc[32];
    #pragma unroll
    for (int p = 0; p < 32; p++) acc[p] = 0ull;

    #pragma unroll 1
    for (int ch = 0; ch < 4; ch++) {
        __syncthreads();   // previous chunk reads done (and wsh visible on first pass)
        #pragma unroll
        for (int p = 0; p < 8; p++) {
            int idx = t + p * 128;                  // 0..1023
            int row = idx >> 4, c4 = idx & 15;
            xs4[row * 17 + c4] = gx[(jT + row) * 64 + ch * 16 + c4];
            ys4[row * 17 + c4] = gy[(iT + row) * 64 + ch * 16 + c4];
        }
        __syncthreads();

        #pragma unroll 8
        for (int k2 = 0; k2 < 32; k2++) {           // 2 k per iter
            u64 w = *(const u64*)&wsh[ch * 32 + k2];
            u64 xv[4];
            #pragma unroll
            for (int a = 0; a < 4; a++)
                xv[a] = *(const u64*)&xsh[(tx + 16 * a) * S2 + k2];
            u64 yv[8];
            #pragma unroll
            for (int b8 = 0; b8 < 8; b8++)
                yv[b8] = *(const u64*)&ysh[(ty + 8 * b8) * S2 + k2];
            #pragma unroll
            for (int b8 = 0; b8 < 8; b8++)
                #pragma unroll
                for (int a = 0; a < 4; a++)
                    step(xv[a], yv[b8], w, acc[b8 * 4 + a]);
        }
    }

    // epilogue: per-pair dot -> exp-sum + diagonal capture
    float le = 0.0f, ld = 0.0f;
    #pragma unroll
    for (int b8 = 0; b8 < 8; b8++) {
        #pragma unroll
        for (int a = 0; a < 4; a++) {
            float lo, hi; up2(acc[b8 * 4 + a], lo, hi);
            float s = lo + hi;
            le += __expf(s);
            if (iT + ty + 8 * b8 == jT + tx + 16 * a) ld += s;
        }
    }

    #pragma unroll
    for (int o = 16; o > 0; o >>= 1) {
        le += __shfl_xor_sync(0xffffffffu, le, o);
        ld += __shfl_xor_sync(0xffffffffu, ld, o);
    }
    int wid = t >> 5, lane = t & 31;
    if (lane == 0) { rr[wid] = le; rr[4 + wid] = ld; }
    __syncthreads();
    if (t == 0) {
        float se = rr[0] + rr[1] + rr[2] + rr[3];
        float sd = rr[4] + rr[5] + rr[6] + rr[7];
        atomicAdd(&g_es, (double)se);
        if (iT == jT) atomicAdd(&g_ds, (double)sd);
        __threadfence();
        unsigned int c = atomicAdd(&g_cnt, 1u);
        if (c == 255u) {
            double es = atomicAdd(&g_es, 0.0);
            double ds = atomicAdd(&g_ds, 0.0);
            double bb = (double)b2[0];
            double lb = ds / (double)NS + bb
                      - exp(bb - 1.0) * es / ((double)NS * (double)NS);
            out[0] = (float)lb;
        }
    }
}

extern "C" void kernel_launch(void* const* d_in, const int* in_sizes, int n_in,
                              void* d_out, int out_size)
{
    (void)in_sizes; (void)n_in; (void)out_size;
    const float* x  = (const float*)d_in[0];
    const float* y  = (const float*)d_in[1];
    const float* W1 = (const float*)d_in[2];
    const float* b1 = (const float*)d_in[3];
    const float* W2 = (const float*)d_in[4];
    const float* b2 = (const float*)d_in[5];

    k_gemm<<<128, 256>>>(x, y, W1, b1);
    k_pair<<<dim3(16, 16), 128>>>(W2, b2, (float*)d_out);
}